// round 6
// baseline (speedup 1.0000x reference)
#include <cuda_runtime.h>
#include <cstdint>

// UniformShardedEmbeddingBags: B=1024, T=32, D=64, E=100000, L=50
// out[bag, :] = sum_{j<50} W[feat[bag*50 + j], bag % 32, :]
//
// R6: persistent-strided grid. 1184 blocks (148 SM x 8 resident) x 256 thr;
// each warp loops over work-ids w' = warp, warp+9472, ... < 32768. At any
// loop iteration all resident warps cover one contiguous 9472-wide window of
// the table-grouped enumeration -> same ~9-table L2 residency as R2 (all
// duplicate draws hit L2; DRAM at the compulsory ~348MB floor), but the
// fractional-wave tail of the 4096-block launch collapses to a 1-bag tail.
// __launch_bounds__(256, 8) pins the reg budget at 32 (R4 showed regs>32
// kills occupancy and DRAM util). Output stored with __stcs so the 8MB of
// writes don't evict gather lines from L2.

namespace {
constexpr int kT = 32;
constexpr int kD = 64;
constexpr int kL = 50;
constexpr int kNumBags = 1024 * kT;                  // 32768
constexpr int kThreads = 256;                        // 8 warps / block
constexpr int kBlocks = 148 * 8;                     // 1184 persistent blocks
constexpr int kTotalWarps = kBlocks * (kThreads / 32);  // 9472
}  // namespace

__global__ __launch_bounds__(kThreads, 8)
void embedding_bag_kernel(const float* __restrict__ weights,
                          const int* __restrict__ features,
                          float* __restrict__ out) {
    const int warp0 = (blockIdx.x * kThreads + threadIdx.x) >> 5;
    const int lane = threadIdx.x & 31;
    constexpr size_t kRowStride2 = (size_t)kT * kD / 2;  // 1024 float2 per e
    const float2* __restrict__ wbase = reinterpret_cast<const float2*>(weights);

    for (int w = warp0; w < kNumBags; w += kTotalWarps) {
        // Table-grouped remap: work-ids [t*1024, (t+1)*1024) pool table t.
        const int bag = ((w & 1023) << 5) | (w >> 10);
        const int table = w >> 10;  // == bag & 31

        const int* __restrict__ idxp = features + bag * kL;

        // Coalesced index fetch: lane j holds draw j; lanes 0..17 draw 32+j.
        const int i0 = __ldg(idxp + lane);
        const int i1 = (lane < kL - 32) ? __ldg(idxp + 32 + lane) : 0;

        const float2* __restrict__ base = wbase + (size_t)table * (kD / 2);

        float2 acc0 = make_float2(0.f, 0.f);
        float2 acc1 = make_float2(0.f, 0.f);

#pragma unroll
        for (int k = 0; k < 32; k += 2) {
            const int ia = __shfl_sync(0xffffffffu, i0, k);
            const int ib = __shfl_sync(0xffffffffu, i0, k + 1);
            const float2 va = __ldg(base + (size_t)ia * kRowStride2 + lane);
            const float2 vb = __ldg(base + (size_t)ib * kRowStride2 + lane);
            acc0.x += va.x; acc0.y += va.y;
            acc1.x += vb.x; acc1.y += vb.y;
        }
#pragma unroll
        for (int k = 0; k < 18; k += 2) {
            const int ia = __shfl_sync(0xffffffffu, i1, k);
            const int ib = __shfl_sync(0xffffffffu, i1, k + 1);
            const float2 va = __ldg(base + (size_t)ia * kRowStride2 + lane);
            const float2 vb = __ldg(base + (size_t)ib * kRowStride2 + lane);
            acc0.x += va.x; acc0.y += va.y;
            acc1.x += vb.x; acc1.y += vb.y;
        }

        float2 r;
        r.x = acc0.x + acc1.x;
        r.y = acc0.y + acc1.y;
        __stcs(reinterpret_cast<float2*>(out) + (size_t)bag * (kD / 2) + lane,
               r);
    }
}

extern "C" void kernel_launch(void* const* d_in, const int* in_sizes, int n_in,
                              void* d_out, int out_size) {
    const float* weights  = (const float*)d_in[0];   // (E, T, D) fp32
    const int*   features = (const int*)d_in[1];     // (B*T*L,) int32
    // d_in[2]: offsets — uniform arange*L, folded into compile-time constants.
    float* out = (float*)d_out;                      // (B, T, D) fp32

    embedding_bag_kernel<<<kBlocks, kThreads>>>(weights, features, out);
}

// round 7
// speedup vs baseline: 1.0442x; 1.0442x over previous
#include <cuda_runtime.h>
#include <cstdint>

// UniformShardedEmbeddingBags: B=1024, T=32, D=64, E=100000, L=50
// out[bag, :] = sum_{j<50} W[feat[bag*50 + j], bag % 32, :]
//
// R7 = exact R2 structure (the proven local optimum: one bag per warp,
// fully-unrolled 50-row gather, float2/LDG.64 coalesced 256B rows, 32 regs,
// occ ~91%, table-grouped bag order keeping ~9 table slices L2-resident so
// all duplicate draws hit L2 -> DRAM at the compulsory ~348MB floor)
// + one delta: __stcs on the output stores, so the 8MB of evict-first
// writes stop competing for L2 ways with the ~92MB gather working set.
// (R5's regression traced to its __ldcs on indices — neighboring bags share
// index lines; that hint is dropped.)
// Lessons enforced: regs <= 32 (R4), no persistent loop (R6 — it breaks
// ptxas's front-batching of the 25 LDGs per bag).

namespace {
constexpr int kT = 32;
constexpr int kD = 64;
constexpr int kL = 50;
constexpr int kNumBags = 1024 * kT;                  // 32768
constexpr int kThreads = 256;                        // 8 warps / block
constexpr int kBlocks = kNumBags / (kThreads / 32);  // 4096
}  // namespace

__global__ __launch_bounds__(kThreads)
void embedding_bag_kernel(const float* __restrict__ weights,
                          const int* __restrict__ features,
                          float* __restrict__ out) {
    const int w = (blockIdx.x * kThreads + threadIdx.x) >> 5;
    const int lane = threadIdx.x & 31;

    // Table-grouped remap: warps [t*1024, (t+1)*1024) all pool table t.
    const int bag = ((w & 1023) << 5) | (w >> 10);
    const int table = w >> 10;  // == bag & 31

    const int* __restrict__ idxp = features + bag * kL;

    // Coalesced index fetch: lane j holds draw j; lanes 0..17 also draw 32+j.
    const int i0 = __ldg(idxp + lane);
    const int i1 = (lane < kL - 32) ? __ldg(idxp + 32 + lane) : 0;

    // Base pointer into this bag's table slice, as float2.
    const float2* __restrict__ base =
        reinterpret_cast<const float2*>(weights) + (size_t)table * (kD / 2);
    constexpr size_t kRowStride2 = (size_t)kT * kD / 2;  // 1024 float2 per e

    float2 acc0 = make_float2(0.f, 0.f);
    float2 acc1 = make_float2(0.f, 0.f);

#pragma unroll
    for (int k = 0; k < 32; k += 2) {
        const int ia = __shfl_sync(0xffffffffu, i0, k);
        const int ib = __shfl_sync(0xffffffffu, i0, k + 1);
        const float2 va = __ldg(base + (size_t)ia * kRowStride2 + lane);
        const float2 vb = __ldg(base + (size_t)ib * kRowStride2 + lane);
        acc0.x += va.x; acc0.y += va.y;
        acc1.x += vb.x; acc1.y += vb.y;
    }
#pragma unroll
    for (int k = 0; k < 18; k += 2) {
        const int ia = __shfl_sync(0xffffffffu, i1, k);
        const int ib = __shfl_sync(0xffffffffu, i1, k + 1);
        const float2 va = __ldg(base + (size_t)ia * kRowStride2 + lane);
        const float2 vb = __ldg(base + (size_t)ib * kRowStride2 + lane);
        acc0.x += va.x; acc0.y += va.y;
        acc1.x += vb.x; acc1.y += vb.y;
    }

    float2 r;
    r.x = acc0.x + acc1.x;
    r.y = acc0.y + acc1.y;
    __stcs(reinterpret_cast<float2*>(out) + (size_t)bag * (kD / 2) + lane, r);
}

extern "C" void kernel_launch(void* const* d_in, const int* in_sizes, int n_in,
                              void* d_out, int out_size) {
    const float* weights  = (const float*)d_in[0];   // (E, T, D) fp32
    const int*   features = (const int*)d_in[1];     // (B*T*L,) int32
    // d_in[2]: offsets — uniform arange*L, folded into compile-time constants.
    float* out = (float*)d_out;                      // (B, T, D) fp32

    embedding_bag_kernel<<<kBlocks, kThreads>>>(weights, features, out);
}